// round 1
// baseline (speedup 1.0000x reference)
#include <cuda_runtime.h>
#include <cstdint>

#define B_ 2
#define S_ 8192
#define D_ 128
#define BM 128
#define BN 64
#define NTHREADS 256
#define QSTR 132
#define KSTR 132
#define VSTR 132
#define PSTR 66
#define SCALE 0.08838834764831843f

typedef unsigned long long u64;

// ---- packed f32x2 helpers (Blackwell: FFMA2 reachable only via PTX) ----
__device__ __forceinline__ u64 fma2(u64 a, u64 b, u64 c) {
    u64 d;
    asm("fma.rn.f32x2 %0, %1, %2, %3;" : "=l"(d) : "l"(a), "l"(b), "l"(c));
    return d;
}
__device__ __forceinline__ u64 mul2(u64 a, u64 b) {
    u64 d;
    asm("mul.rn.f32x2 %0, %1, %2;" : "=l"(d) : "l"(a), "l"(b));
    return d;
}
__device__ __forceinline__ u64 bcast2(float x) {
    u64 d; unsigned xi = __float_as_uint(x);
    asm("mov.b64 %0, {%1, %2};" : "=l"(d) : "r"(xi), "r"(xi));
    return d;
}
__device__ __forceinline__ float2 unpack2(u64 v) {
    unsigned lo, hi;
    asm("mov.b64 {%0, %1}, %2;" : "=r"(lo), "=r"(hi) : "l"(v));
    return make_float2(__uint_as_float(lo), __uint_as_float(hi));
}

// smem layout (floats)
#define SQ_OFF 0
#define SK_OFF (BM * QSTR)
#define SV_OFF (SK_OFF + BN * KSTR)
#define SP_OFF (SV_OFF + BN * VSTR)
#define SMEM_FLOATS (SP_OFF + BM * PSTR)
#define SMEM_BYTES (SMEM_FLOATS * 4)

__global__ void __launch_bounds__(NTHREADS, 1)
attn_kernel(const float* __restrict__ Q, const float* __restrict__ K,
            const float* __restrict__ V, float* __restrict__ Out)
{
    extern __shared__ float sm[];
    float* sQ = sm + SQ_OFF;
    float* sK = sm + SK_OFF;
    float* sV = sm + SV_OFF;
    float* sP = sm + SP_OFF;

    const int tid = threadIdx.x;
    const int ty  = tid >> 3;   // 0..31 : owns q-rows {ty, ty+32, ty+64, ty+96}
    const int tx  = tid & 7;    // 0..7  : owns score cols {tx + 8j}, out cols {tx*4 + 32cc}

    const int b  = blockIdx.y;
    const int qt = blockIdx.x;

    const float* Qb = Q + ((size_t)b * S_ + (size_t)qt * BM) * D_;
    const float* Kb = K + (size_t)b * S_ * D_;
    const float* Vb = V + (size_t)b * S_ * D_;

    // ---- load Q tile once, pre-scaled by 1/sqrt(D) ----
    for (int i = tid; i < BM * (D_ / 4); i += NTHREADS) {
        int row = i >> 5;
        int c   = (i & 31) << 2;
        float4 q = *reinterpret_cast<const float4*>(Qb + row * D_ + c);
        q.x *= SCALE; q.y *= SCALE; q.z *= SCALE; q.w *= SCALE;
        *reinterpret_cast<float4*>(sQ + row * QSTR + c) = q;
    }

    u64  O2[4][8];
    float mrow[4], lrow[4];
    #pragma unroll
    for (int r = 0; r < 4; ++r) {
        mrow[r] = -3.0e38f;
        lrow[r] = 0.0f;
        #pragma unroll
        for (int c = 0; c < 8; ++c) O2[r][c] = 0ull;
    }

    __syncthreads();

    const float* qbase = sQ + ty * QSTR;
    const float* kbase = sK + tx * KSTR;
    const float* pbase = sP + ty * PSTR;
    const float* vbase = sV + tx * 4;

    for (int t = 0; t < S_ / BN; ++t) {
        // ---- stage K/V tile into smem ----
        const float* Kt = Kb + (size_t)t * BN * D_;
        const float* Vt = Vb + (size_t)t * BN * D_;
        for (int i = tid; i < BN * (D_ / 4); i += NTHREADS) {
            int row = i >> 5;
            int c   = (i & 31) << 2;
            *reinterpret_cast<float4*>(sK + row * KSTR + c) =
                *reinterpret_cast<const float4*>(Kt + row * D_ + c);
            *reinterpret_cast<float4*>(sV + row * VSTR + c) =
                *reinterpret_cast<const float4*>(Vt + row * D_ + c);
        }
        __syncthreads();

        // ---- S = Q K^T : packed along d (even/odd partial sums) ----
        u64 s2[4][8];
        #pragma unroll
        for (int r = 0; r < 4; ++r)
            #pragma unroll
            for (int j = 0; j < 8; ++j) s2[r][j] = 0ull;

        #pragma unroll 2
        for (int d = 0; d < D_; d += 4) {
            ulonglong2 qv[4];
            #pragma unroll
            for (int r = 0; r < 4; ++r)
                qv[r] = *reinterpret_cast<const ulonglong2*>(qbase + r * 32 * QSTR + d);
            #pragma unroll
            for (int j = 0; j < 8; ++j) {
                ulonglong2 kv = *reinterpret_cast<const ulonglong2*>(kbase + j * 8 * KSTR + d);
                #pragma unroll
                for (int r = 0; r < 4; ++r) {
                    s2[r][j] = fma2(qv[r].x, kv.x, s2[r][j]);
                    s2[r][j] = fma2(qv[r].y, kv.y, s2[r][j]);
                }
            }
        }

        // ---- online softmax (row state fully in registers) ----
        #pragma unroll
        for (int r = 0; r < 4; ++r) {
            float s[8];
            float mt = -3.0e38f;
            #pragma unroll
            for (int j = 0; j < 8; ++j) {
                float2 p = unpack2(s2[r][j]);
                s[j] = p.x + p.y;
                mt = fmaxf(mt, s[j]);
            }
            mt = fmaxf(mt, __shfl_xor_sync(0xffffffffu, mt, 1));
            mt = fmaxf(mt, __shfl_xor_sync(0xffffffffu, mt, 2));
            mt = fmaxf(mt, __shfl_xor_sync(0xffffffffu, mt, 4));
            float mn  = fmaxf(mrow[r], mt);
            float fac = __expf(mrow[r] - mn);
            mrow[r] = mn;

            float sum = 0.0f;
            float* prow = sP + (ty + 32 * r) * PSTR;
            #pragma unroll
            for (int j = 0; j < 8; ++j) {
                float p = __expf(s[j] - mn);
                sum += p;
                prow[tx + 8 * j] = p;
            }
            sum += __shfl_xor_sync(0xffffffffu, sum, 1);
            sum += __shfl_xor_sync(0xffffffffu, sum, 2);
            sum += __shfl_xor_sync(0xffffffffu, sum, 4);
            lrow[r] = lrow[r] * fac + sum;

            // rescale output accumulators by exp(m_old - m_new)
            u64 f2 = bcast2(fac);
            #pragma unroll
            for (int c = 0; c < 8; ++c) O2[r][c] = mul2(O2[r][c], f2);
        }
        __syncthreads();

        // ---- O += P V : packed along output columns ----
        #pragma unroll 2
        for (int kk = 0; kk < BN; ++kk) {
            u64 pd[4];
            #pragma unroll
            for (int r = 0; r < 4; ++r)
                pd[r] = bcast2(pbase[r * 32 * PSTR + kk]);
            #pragma unroll
            for (int cc = 0; cc < 4; ++cc) {
                ulonglong2 vv = *reinterpret_cast<const ulonglong2*>(vbase + kk * VSTR + cc * 32);
                #pragma unroll
                for (int r = 0; r < 4; ++r) {
                    O2[r][2 * cc]     = fma2(pd[r], vv.x, O2[r][2 * cc]);
                    O2[r][2 * cc + 1] = fma2(pd[r], vv.y, O2[r][2 * cc + 1]);
                }
            }
        }
        __syncthreads();
    }

    // ---- epilogue: normalize and store ----
    float* Ob = Out + ((size_t)b * S_ + (size_t)qt * BM) * D_;
    #pragma unroll
    for (int r = 0; r < 4; ++r) {
        float inv = 1.0f / lrow[r];
        int row = ty + 32 * r;
        #pragma unroll
        for (int cc = 0; cc < 4; ++cc) {
            float2 a  = unpack2(O2[r][2 * cc]);
            float2 bb = unpack2(O2[r][2 * cc + 1]);
            float4 o  = make_float4(a.x * inv, a.y * inv, bb.x * inv, bb.y * inv);
            *reinterpret_cast<float4*>(Ob + row * D_ + tx * 4 + cc * 32) = o;
        }
    }
}

extern "C" void kernel_launch(void* const* d_in, const int* in_sizes, int n_in,
                              void* d_out, int out_size)
{
    const float* Q = (const float*)d_in[0];
    const float* K = (const float*)d_in[1];
    const float* V = (const float*)d_in[2];
    float* O = (float*)d_out;

    cudaFuncSetAttribute(attn_kernel,
                         cudaFuncAttributeMaxDynamicSharedMemorySize, SMEM_BYTES);

    dim3 grid(S_ / BM, B_);
    attn_kernel<<<grid, NTHREADS, SMEM_BYTES>>>(Q, K, V, O);
}